// round 11
// baseline (speedup 1.0000x reference)
#include <cuda_runtime.h>
#include <cuda_fp16.h>
#include <cstdint>

// SoftPixelRadiusCNN:
//   d      = sqrt(distsq + EPS)
//   w_i(k) = exp(-scaler * (d_k - i/ls)^2),  scaler = 10*ls*SUBDIV
//   out[v, i*F + f] = sum_k w_i(k) * features[nidx[v,k], f] / (sum_k w_i(k) + EPS)
// V=100000, K=32, F=64, SUBDIV=3.
//
// R11 = R10 with portable fp16 bit-casts (no __half2_as_uint/__uint_as_half2).
// Theory: the ~79% L1TEX ceiling of R5/R9 is the gather miss path (64
// wavefronts/vertex); fp16-compressed features halve it to 32. Prep kernel
// writes a __device__ static fp16 copy; main kernel gathers uint2 (4 halves)
// per lane. fp32 accumulation, 256-thread blocks, no reg cap.

#define K_NEIGH 32
#define F_DIM   64
#define SUBDIV  3
#define EPSV    1e-6f
#define OUT_F   (SUBDIV * F_DIM)
#define FULLM   0xFFFFFFFFu

#define V_CAP   100352                       // static fp16 buffer capacity (rows)
__device__ __half g_feat16[(size_t)V_CAP * F_DIM];   // 12.85 MB module-static scratch

// ---------------------------------------------------------------- convert
__global__ __launch_bounds__(256)
void convert_kernel(const float* __restrict__ features, int n4 /* V*F/4 */)
{
    const int stride = gridDim.x * blockDim.x;
    for (int i = blockIdx.x * blockDim.x + threadIdx.x; i < n4; i += stride) {
        const float4 x = reinterpret_cast<const float4*>(features)[i];
        __half2 lo = __floats2half2_rn(x.x, x.y);
        __half2 hi = __floats2half2_rn(x.z, x.w);
        const uint32_t lo_u = *reinterpret_cast<const uint32_t*>(&lo);
        const uint32_t hi_u = *reinterpret_cast<const uint32_t*>(&hi);
        reinterpret_cast<uint2*>(g_feat16)[i] = make_uint2(lo_u, hi_u);
    }
}

// ---------------------------------------------------------------- main (fp16 gather)
__global__ __launch_bounds__(256)
void softpixel_kernel_h(const float* __restrict__ distsq,
                        const int*   __restrict__ nidx,
                        const float* __restrict__ ls_ptr,
                        float*       __restrict__ out,
                        int V)
{
    const int lane   = threadIdx.x & 31;
    const int half   = lane >> 4;      // 0 or 1
    const int t      = lane & 15;      // 4-col group within the half
    const int warp0  = (blockIdx.x * blockDim.x + threadIdx.x) >> 5;
    const int nwarps = (gridDim.x * blockDim.x) >> 5;

    const float ls     = __ldg(ls_ptr);
    const float scaler = 10.0f * ls * (float)SUBDIV;
    const float inv_ls = 1.0f / ls;

    for (int v = warp0; v < V; v += nwarps) {
        // --- per-lane neighbor (k = lane): distance, index, 3 bin weights ---
        const float dsq    = __ldg(distsq + (size_t)v * K_NEIGH + lane);
        const int   my_idx = __ldg(nidx   + (size_t)v * K_NEIGH + lane);
        const float d  = sqrtf(dsq + EPSV);
        const float t1 = d - inv_ls;
        const float t2 = d - 2.0f * inv_ls;
        const float w0 = __expf(-scaler * d  * d);
        const float w1 = __expf(-scaler * t1 * t1);
        const float w2 = __expf(-scaler * t2 * t2);

        // --- gather loop: 2 neighbors/iteration (one per half-warp);
        //     lane loads 4 fp16 cols (uint2, 8B) -> 128B per half-warp row ---
        float4 a0 = make_float4(0.f, 0.f, 0.f, 0.f);
        float4 a1 = make_float4(0.f, 0.f, 0.f, 0.f);
        float4 a2 = make_float4(0.f, 0.f, 0.f, 0.f);
        float s0 = 0.f, s1 = 0.f, s2 = 0.f;
        const __half* fbase = g_feat16 + (size_t)4 * t;

        int kj = half;
        #pragma unroll
        for (int j = 0; j < K_NEIGH / 2; ++j, kj += 2) {
            const int   ik = __shfl_sync(FULLM, my_idx, kj);
            const float b0 = __shfl_sync(FULLM, w0, kj);
            const float b1 = __shfl_sync(FULLM, w1, kj);
            const float b2 = __shfl_sync(FULLM, w2, kj);
            const uint2 p = *reinterpret_cast<const uint2*>(fbase + (size_t)ik * F_DIM);
            const __half2 hxy = *reinterpret_cast<const __half2*>(&p.x);
            const __half2 hzw = *reinterpret_cast<const __half2*>(&p.y);
            const float2 fxy = __half22float2(hxy);
            const float2 fzw = __half22float2(hzw);
            s0 += b0; s1 += b1; s2 += b2;
            a0.x = fmaf(b0, fxy.x, a0.x); a0.y = fmaf(b0, fxy.y, a0.y);
            a0.z = fmaf(b0, fzw.x, a0.z); a0.w = fmaf(b0, fzw.y, a0.w);
            a1.x = fmaf(b1, fxy.x, a1.x); a1.y = fmaf(b1, fxy.y, a1.y);
            a1.z = fmaf(b1, fzw.x, a1.z); a1.w = fmaf(b1, fzw.y, a1.w);
            a2.x = fmaf(b2, fxy.x, a2.x); a2.y = fmaf(b2, fxy.y, a2.y);
            a2.z = fmaf(b2, fzw.x, a2.z); a2.w = fmaf(b2, fzw.y, a2.w);
        }

        // --- combine even-k / odd-k partials: 15 SHFLs ---
        a0.x += __shfl_xor_sync(FULLM, a0.x, 16); a0.y += __shfl_xor_sync(FULLM, a0.y, 16);
        a0.z += __shfl_xor_sync(FULLM, a0.z, 16); a0.w += __shfl_xor_sync(FULLM, a0.w, 16);
        a1.x += __shfl_xor_sync(FULLM, a1.x, 16); a1.y += __shfl_xor_sync(FULLM, a1.y, 16);
        a1.z += __shfl_xor_sync(FULLM, a1.z, 16); a1.w += __shfl_xor_sync(FULLM, a1.w, 16);
        a2.x += __shfl_xor_sync(FULLM, a2.x, 16); a2.y += __shfl_xor_sync(FULLM, a2.y, 16);
        a2.z += __shfl_xor_sync(FULLM, a2.z, 16); a2.w += __shfl_xor_sync(FULLM, a2.w, 16);
        s0   += __shfl_xor_sync(FULLM, s0,   16);
        s1   += __shfl_xor_sync(FULLM, s1,   16);
        s2   += __shfl_xor_sync(FULLM, s2,   16);

        // --- write (V, 3*F): half 0 -> bins 0,2; half 1 -> bin 1 ---
        float* obase = out + (size_t)v * OUT_F + 4 * t;
        if (half == 0) {
            const float r0 = 1.0f / (s0 + EPSV);
            const float r2 = 1.0f / (s2 + EPSV);
            *reinterpret_cast<float4*>(obase) =
                make_float4(a0.x * r0, a0.y * r0, a0.z * r0, a0.w * r0);
            *reinterpret_cast<float4*>(obase + 2 * F_DIM) =
                make_float4(a2.x * r2, a2.y * r2, a2.z * r2, a2.w * r2);
        } else {
            const float r1 = 1.0f / (s1 + EPSV);
            *reinterpret_cast<float4*>(obase + F_DIM) =
                make_float4(a1.x * r1, a1.y * r1, a1.z * r1, a1.w * r1);
        }
    }
}

// ---------------------------------------------------------------- fallback (fp32 gather)
__global__ __launch_bounds__(256)
void softpixel_kernel_f(const float* __restrict__ features,
                        const float* __restrict__ distsq,
                        const int*   __restrict__ nidx,
                        const float* __restrict__ ls_ptr,
                        float*       __restrict__ out,
                        int V)
{
    const int lane   = threadIdx.x & 31;
    const int half   = lane >> 4;
    const int t      = lane & 15;
    const int warp0  = (blockIdx.x * blockDim.x + threadIdx.x) >> 5;
    const int nwarps = (gridDim.x * blockDim.x) >> 5;

    const float ls     = __ldg(ls_ptr);
    const float scaler = 10.0f * ls * (float)SUBDIV;
    const float inv_ls = 1.0f / ls;

    for (int v = warp0; v < V; v += nwarps) {
        const float dsq    = __ldg(distsq + (size_t)v * K_NEIGH + lane);
        const int   my_idx = __ldg(nidx   + (size_t)v * K_NEIGH + lane);
        const float d  = sqrtf(dsq + EPSV);
        const float t1 = d - inv_ls;
        const float t2 = d - 2.0f * inv_ls;
        const float w0 = __expf(-scaler * d  * d);
        const float w1 = __expf(-scaler * t1 * t1);
        const float w2 = __expf(-scaler * t2 * t2);

        float4 a0 = make_float4(0.f, 0.f, 0.f, 0.f);
        float4 a1 = make_float4(0.f, 0.f, 0.f, 0.f);
        float4 a2 = make_float4(0.f, 0.f, 0.f, 0.f);
        float s0 = 0.f, s1 = 0.f, s2 = 0.f;
        const float* fbase = features + (size_t)4 * t;

        int kj = half;
        #pragma unroll
        for (int j = 0; j < K_NEIGH / 2; ++j, kj += 2) {
            const int   ik = __shfl_sync(FULLM, my_idx, kj);
            const float b0 = __shfl_sync(FULLM, w0, kj);
            const float b1 = __shfl_sync(FULLM, w1, kj);
            const float b2 = __shfl_sync(FULLM, w2, kj);
            const float4 f = *reinterpret_cast<const float4*>(fbase + (size_t)ik * F_DIM);
            s0 += b0; s1 += b1; s2 += b2;
            a0.x = fmaf(b0, f.x, a0.x); a0.y = fmaf(b0, f.y, a0.y);
            a0.z = fmaf(b0, f.z, a0.z); a0.w = fmaf(b0, f.w, a0.w);
            a1.x = fmaf(b1, f.x, a1.x); a1.y = fmaf(b1, f.y, a1.y);
            a1.z = fmaf(b1, f.z, a1.z); a1.w = fmaf(b1, f.w, a1.w);
            a2.x = fmaf(b2, f.x, a2.x); a2.y = fmaf(b2, f.y, a2.y);
            a2.z = fmaf(b2, f.z, a2.z); a2.w = fmaf(b2, f.w, a2.w);
        }

        a0.x += __shfl_xor_sync(FULLM, a0.x, 16); a0.y += __shfl_xor_sync(FULLM, a0.y, 16);
        a0.z += __shfl_xor_sync(FULLM, a0.z, 16); a0.w += __shfl_xor_sync(FULLM, a0.w, 16);
        a1.x += __shfl_xor_sync(FULLM, a1.x, 16); a1.y += __shfl_xor_sync(FULLM, a1.y, 16);
        a1.z += __shfl_xor_sync(FULLM, a1.z, 16); a1.w += __shfl_xor_sync(FULLM, a1.w, 16);
        a2.x += __shfl_xor_sync(FULLM, a2.x, 16); a2.y += __shfl_xor_sync(FULLM, a2.y, 16);
        a2.z += __shfl_xor_sync(FULLM, a2.z, 16); a2.w += __shfl_xor_sync(FULLM, a2.w, 16);
        s0   += __shfl_xor_sync(FULLM, s0,   16);
        s1   += __shfl_xor_sync(FULLM, s1,   16);
        s2   += __shfl_xor_sync(FULLM, s2,   16);

        float* obase = out + (size_t)v * OUT_F + 4 * t;
        if (half == 0) {
            const float r0 = 1.0f / (s0 + EPSV);
            const float r2 = 1.0f / (s2 + EPSV);
            *reinterpret_cast<float4*>(obase) =
                make_float4(a0.x * r0, a0.y * r0, a0.z * r0, a0.w * r0);
            *reinterpret_cast<float4*>(obase + 2 * F_DIM) =
                make_float4(a2.x * r2, a2.y * r2, a2.z * r2, a2.w * r2);
        } else {
            const float r1 = 1.0f / (s1 + EPSV);
            *reinterpret_cast<float4*>(obase + F_DIM) =
                make_float4(a1.x * r1, a1.y * r1, a1.z * r1, a1.w * r1);
        }
    }
}

extern "C" void kernel_launch(void* const* d_in, const int* in_sizes, int n_in,
                              void* d_out, int out_size)
{
    const float* features = (const float*)d_in[0];
    const float* distsq   = (const float*)d_in[1];
    const int*   nidx     = (const int*)  d_in[2];
    const float* ls       = (const float*)d_in[3];
    float*       out      = (float*)d_out;

    int V = out_size / OUT_F;
    if (V <= 0) V = in_sizes[1] / K_NEIGH;

    const int threads = 256;
    int blocks = (V * 32 + threads - 1) / threads;
    if (blocks < 1) blocks = 1;

    if (V <= V_CAP) {
        const int n4 = (V * F_DIM) / 4;               // float4 count
        int cblocks = (n4 + threads - 1) / threads;
        if (cblocks > 4096) cblocks = 4096;
        if (cblocks < 1) cblocks = 1;
        convert_kernel<<<cblocks, threads>>>(features, n4);
        softpixel_kernel_h<<<blocks, threads>>>(distsq, nidx, ls, out, V);
    } else {
        softpixel_kernel_f<<<blocks, threads>>>(features, distsq, nidx, ls, out, V);
    }
}